// round 15
// baseline (speedup 1.0000x reference)
#include <cuda_runtime.h>
#include <cuda.h>
#include <cuda_bf16.h>
#include <cstdint>
#include <math.h>

#define N_ROWS 16384
#define DIM    512
#define SCALEF 14.285714285714286f
#define C1F    20.609928468897677f   /* SCALE * log2(e) */
#define LN2F   0.6931471805599453f

#if defined(__CUDA_ARCH__) && (defined(__CUDA_ARCH_FEAT_SM103_ALL) || defined(__CUDA_ARCH_FEAT_SM100_ALL) || defined(__CUDA_ARCH_FEAT_SM101_ALL))
#define HAS_TC 1
#else
#define HAS_TC 0
#endif

#define NPAIRS 74
#define GRID_TC 148
#define NUNITS 512
#define TPU    16
#define NTHR   576

#define BAR_AFULL   0
#define BAR_BFULL(c)   (8  + 8*(c))    /* 8..32 */
#define BAR_BEMPTY(c)  (40 + 8*(c))    /* 40..64 */
#define BAR_DEMPTY(b)  (72 + 8*(b))    /* 72,80,88,96 */
#define BAR_DFULL(b)   (104 + 8*(b))   /* 104,112,120,128 */
#define SM_TPTR     136
#define SM_A        1024
#define SM_B        (1024 + 131072)
#define SM_CM       (1024 + 131072 + 65536)
#define SM_TB       (SM_CM + 8192)
#define SMEM_TOTAL_TC  (SM_TB + 16 * 1152)

#define MMA_IDESC 0x10200490u   /* f32 acc, bf16 x bf16, M=256, N=128 */

__device__ __align__(1024) __nv_bfloat16 g_img_bf[(size_t)N_ROWS * DIM];
__device__ __align__(1024) __nv_bfloat16 g_txt_bf[(size_t)N_ROWS * DIM];
__device__ float2 g_rowp[(size_t)NUNITS * 4 * 256];
__device__ float2 g_colp[(size_t)128 * N_ROWS];
__device__ float  g_lse[2 * N_ROWS];
__device__ float  g_diag[N_ROWS];
__device__ double g_part[32];

__device__ __forceinline__ float ex2f(float x) { float y; asm("ex2.approx.f32 %0, %1;" : "=f"(y) : "f"(x)); return y; }
__device__ __forceinline__ float lg2f(float x) { float y; asm("lg2.approx.f32 %0, %1;" : "=f"(y) : "f"(x)); return y; }

__global__ void conv_diag_kernel(const float* __restrict__ img, const float* __restrict__ txt) {
    const int row  = blockIdx.x * 8 + (threadIdx.x >> 5);
    const int lane = threadIdx.x & 31;
    const float4* ai = (const float4*)(img + (size_t)row * DIM);
    const float4* bi = (const float4*)(txt + (size_t)row * DIM);
    __nv_bfloat162* ao = (__nv_bfloat162*)(g_img_bf + (size_t)row * DIM);
    __nv_bfloat162* bo = (__nv_bfloat162*)(g_txt_bf + (size_t)row * DIM);
    float dot = 0.f;
    #pragma unroll
    for (int t = 0; t < 4; t++) {
        const int i = lane + 32 * t;
        float4 a = ai[i], b = bi[i];
        ao[2 * i]     = __float22bfloat162_rn(make_float2(a.x, a.y));
        ao[2 * i + 1] = __float22bfloat162_rn(make_float2(a.z, a.w));
        bo[2 * i]     = __float22bfloat162_rn(make_float2(b.x, b.y));
        bo[2 * i + 1] = __float22bfloat162_rn(make_float2(b.z, b.w));
        dot += a.x * b.x + a.y * b.y + a.z * b.z + a.w * b.w;
    }
    #pragma unroll
    for (int o = 16; o; o >>= 1) dot += __shfl_xor_sync(0xFFFFFFFFu, dot, o);
    if (lane == 0) g_diag[row] = SCALEF * dot;
}

#if HAS_TC
__device__ __forceinline__ uint32_t smem_u32(const void* p) {
    uint32_t a;
    asm("{ .reg .u64 t; cvta.to.shared.u64 t, %1; cvt.u32.u64 %0, t; }" : "=r"(a) : "l"(p));
    return a;
}
__device__ __forceinline__ uint32_t elect_one() {
    uint32_t pred;
    asm volatile("{\n\t.reg .pred p;\n\telect.sync _|p, 0xFFFFFFFF;\n\tselp.b32 %0, 1, 0, p;\n\t}" : "=r"(pred));
    return pred;
}
__device__ __forceinline__ uint32_t ctarank() {
    uint32_t r; asm("mov.u32 %0, %%cluster_ctarank;" : "=r"(r)); return r;
}

#define MBARRIER_INIT(addr, cnt) \
    asm volatile("mbarrier.init.shared.b64 [%0], %1;" :: "r"((uint32_t)(addr)), "r"((uint32_t)(cnt)) : "memory")
#define MBARRIER_EXPECT_TX(addr, bytes) \
    asm volatile("mbarrier.arrive.expect_tx.shared.b64 _, [%0], %1;" :: "r"((uint32_t)(addr)), "r"((uint32_t)(bytes)) : "memory")
#define MBARRIER_ARRIVE_LEADER(addr) \
    asm volatile("{\n\t.reg .b32 la;\n\tand.b32 la, %0, 0xFEFFFFFF;\n\t" \
                 "mbarrier.arrive.shared::cluster.b64 _, [la];\n\t}" :: "r"((uint32_t)(addr)) : "memory")
#define MBARRIER_WAIT_PARITY(addr, par) do {                                      \
    uint32_t _m = (uint32_t)(addr), _p = (uint32_t)(par), _d;                     \
    asm volatile("{\n\t.reg .pred p;\n\t"                                         \
        "mbarrier.try_wait.parity.acquire.cta.shared::cta.b64 p, [%1], %2;\n\t"   \
        "selp.b32 %0, 1, 0, p;\n\t}" : "=r"(_d) : "r"(_m), "r"(_p) : "memory");   \
    if (!_d) {                                                                    \
        asm volatile("{\n\t.reg .pred P1;\n\t"                                    \
            "WL_%=:\n\t"                                                          \
            "mbarrier.try_wait.parity.acquire.cta.shared::cta.b64 P1, [%0], %1, 0x989680;\n\t" \
            "@P1 bra.uni WD_%=;\n\t"                                              \
            "bra.uni WL_%=;\n\t"                                                  \
            "WD_%=:\n\t}" :: "r"(_m), "r"(_p) : "memory");                        \
    } } while (0)

#define CLUSTER_SYNC() do { \
    asm volatile("barrier.cluster.arrive.aligned;" ::: "memory"); \
    asm volatile("barrier.cluster.wait.aligned;"   ::: "memory"); } while (0)

#define TCGEN05_ALLOC_CG2(sm, n) \
    asm volatile("tcgen05.alloc.cta_group::2.sync.aligned.shared::cta.b32 [%0], %1;" \
                 :: "r"((uint32_t)(sm)), "r"((uint32_t)(n)) : "memory")
#define TCGEN05_DEALLOC_CG2(t, n) \
    asm volatile("tcgen05.dealloc.cta_group::2.sync.aligned.b32 %0, %1;" :: "r"(t), "r"((uint32_t)(n)))
#define TCGEN05_RELINQ_CG2() \
    asm volatile("tcgen05.relinquish_alloc_permit.cta_group::2.sync.aligned;")
#define TCGEN05_COMMIT_MC_CG2(bar, mask) \
    asm volatile("tcgen05.commit.cta_group::2.mbarrier::arrive::one.shared::cluster.multicast::cluster.b64 [%0], %1;" \
                 :: "r"((uint32_t)(bar)), "h"((uint16_t)(mask)) : "memory")
#define TCGEN05_FENCE_BEFORE() asm volatile("tcgen05.fence::before_thread_sync;" ::: "memory")
#define TCGEN05_FENCE_AFTER()  asm volatile("tcgen05.fence::after_thread_sync;" ::: "memory")
#define TCGEN05_WAIT_LD()      asm volatile("tcgen05.wait::ld.sync.aligned;" ::: "memory")

#define TCGEN05_LD_32X32B_X32(r, ta) \
    asm volatile("tcgen05.ld.sync.aligned.32x32b.x32.b32 " \
        "{%0, %1, %2, %3, %4, %5, %6, %7, %8, %9, %10, %11, %12, %13, %14, %15, " \
        " %16, %17, %18, %19, %20, %21, %22, %23, %24, %25, %26, %27, %28, %29, %30, %31}, [%32];" \
        : "=r"((r)[0]),  "=r"((r)[1]),  "=r"((r)[2]),  "=r"((r)[3]), \
          "=r"((r)[4]),  "=r"((r)[5]),  "=r"((r)[6]),  "=r"((r)[7]), \
          "=r"((r)[8]),  "=r"((r)[9]),  "=r"((r)[10]), "=r"((r)[11]), \
          "=r"((r)[12]), "=r"((r)[13]), "=r"((r)[14]), "=r"((r)[15]), \
          "=r"((r)[16]), "=r"((r)[17]), "=r"((r)[18]), "=r"((r)[19]), \
          "=r"((r)[20]), "=r"((r)[21]), "=r"((r)[22]), "=r"((r)[23]), \
          "=r"((r)[24]), "=r"((r)[25]), "=r"((r)[26]), "=r"((r)[27]), \
          "=r"((r)[28]), "=r"((r)[29]), "=r"((r)[30]), "=r"((r)[31]) \
        : "r"(ta))

#define TMA_LOAD_3D_CG2(dst, map, x, y, z, bar) \
    asm volatile("{\n\t.reg .b32 lb;\n\tand.b32 lb, %5, 0xFEFFFFFF;\n\t" \
        "cp.async.bulk.tensor.3d.cta_group::2.shared::cluster.global" \
        ".tile.mbarrier::complete_tx::bytes [%0], [%1, {%2, %3, %4}], [lb];\n\t}" \
        :: "r"((uint32_t)(dst)), "l"(map), "r"((int32_t)(x)), "r"((int32_t)(y)), "r"((int32_t)(z)), \
           "r"((uint32_t)(bar)) : "memory")

static constexpr uint64_t SMEM_DESC_BASE_SW128 =
    (uint64_t(2)  << 61) | (uint64_t(1) << 46) | (uint64_t(64) << 32) | (uint64_t(1) << 16);
#define MAKE_SMEM_DESC(a) (SMEM_DESC_BASE_SW128 | ((uint64_t)((a) >> 4) & 0x3FFF))

__device__ __forceinline__ void mma_f16_ss_cg2(uint32_t d, uint64_t a, uint64_t b,
                                               uint32_t idesc, uint32_t en) {
    asm volatile("{\n\t.reg .pred p;\n\tsetp.ne.u32 p, %5, 0;\n\t"
        "tcgen05.mma.cta_group::2.kind::f16 [%0], %1, %2, %3, "
        "{%4, %4, %4, %4, %4, %4, %4, %4}, p;\n\t}"
        :: "r"(d), "l"(a), "l"(b), "r"(idesc), "r"(0u), "r"(en) : "memory");
}
#endif  // HAS_TC helpers

extern __shared__ char smem_raw_g[];

__global__ void __launch_bounds__(NTHR, 1) __cluster_dims__(2, 1, 1)
clip_gemm_tc(const __grid_constant__ CUtensorMap tm_img,
             const __grid_constant__ CUtensorMap tm_txt) {
#if HAS_TC
    uint32_t sb = smem_u32(smem_raw_g);
    const int tid  = threadIdx.x;
    const int wid  = tid >> 5;
    const int lane = tid & 31;
    const uint32_t rank = ctarank();
    const int p = blockIdx.x >> 1;
    const int u0 = (p * NUNITS) / NPAIRS;
    const int u1 = ((p + 1) * NUNITS) / NPAIRS;

    if (wid == 16) TCGEN05_ALLOC_CG2(sb + SM_TPTR, 512);
    if (tid == 0) {
        MBARRIER_INIT(sb + BAR_AFULL, 1);
        #pragma unroll
        for (int c = 0; c < 4; c++) {
            MBARRIER_INIT(sb + BAR_BFULL(c), 1);
            MBARRIER_INIT(sb + BAR_BEMPTY(c), 1);
            MBARRIER_INIT(sb + BAR_DEMPTY(c), 32);
            MBARRIER_INIT(sb + BAR_DFULL(c), 1);
        }
    }
    __syncthreads();
    uint32_t tmem;
    asm volatile("ld.shared.b32 %0, [%1];" : "=r"(tmem) : "r"(sb + SM_TPTR));
    CLUSTER_SYNC();

    if (wid == 16) {
        // ---------------- producer: TMA issue ----------------
        if (elect_one()) {
            int gt = 0, prev_band = -1;
            for (int u = u0; u < u1; u++) {
                const int band = u >> 3, chunk = u & 7;
                if (band != prev_band) {
                    if (gt > 0) MBARRIER_WAIT_PARITY(sb + BAR_BEMPTY(3), (gt & 1) ^ 1);
                    if (rank == 0) MBARRIER_EXPECT_TX(sb + BAR_AFULL, 262144);
                    const int arow = band * 256 + (int)rank * 128;
                    #pragma unroll
                    for (int k8 = 0; k8 < 8; k8++)
                        #pragma unroll
                        for (int r64 = 0; r64 < 2; r64++)
                            TMA_LOAD_3D_CG2(sb + SM_A + k8 * 16384 + r64 * 8192, &tm_img,
                                            k8 * 64, arow + r64 * 64, 0, sb + BAR_AFULL);
                    prev_band = band;
                }
                for (int k = 0; k < TPU; k++) {
                    const int tc = chunk * TPU + k;
                    #pragma unroll
                    for (int c = 0; c < 4; c++) {
                        MBARRIER_WAIT_PARITY(sb + BAR_BEMPTY(c), (gt & 1) ^ 1);
                        if (rank == 0) MBARRIER_EXPECT_TX(sb + BAR_BFULL(c), 32768);
                        const int y = tc * 128 + (int)rank * 64;
                        TMA_LOAD_3D_CG2(sb + SM_B + c * 16384,        &tm_txt, c * 128,      y, 0, sb + BAR_BFULL(c));
                        TMA_LOAD_3D_CG2(sb + SM_B + c * 16384 + 8192, &tm_txt, c * 128 + 64, y, 0, sb + BAR_BFULL(c));
                    }
                    gt++;
                }
            }
        }
    } else if (wid == 17) {
        // ---------------- MMA issuer (leader only), 4 D buffers ----------------
        if (rank == 0 && elect_one()) {
            int gt = 0, lb = 0, prev_band = -1;
            const uint64_t adb = MAKE_SMEM_DESC(sb + SM_A);
            for (int u = u0; u < u1; u++) {
                const int band = u >> 3;
                if (band != prev_band) {
                    MBARRIER_WAIT_PARITY(sb + BAR_AFULL, lb & 1);
                    lb++; prev_band = band;
                }
                for (int k = 0; k < TPU; k++) {
                    const int b = gt & 3;
                    MBARRIER_WAIT_PARITY(sb + BAR_DEMPTY(b), ((gt >> 2) & 1) ^ 1);
                    TCGEN05_FENCE_AFTER();
                    #pragma unroll
                    for (int c = 0; c < 4; c++) {
                        MBARRIER_WAIT_PARITY(sb + BAR_BFULL(c), gt & 1);
                        const uint64_t bdb = MAKE_SMEM_DESC(sb + SM_B + c * 16384);
                        #pragma unroll
                        for (int ks = 0; ks < 8; ks++) {
                            const int gk = c * 8 + ks;
                            mma_f16_ss_cg2(tmem + b * 128,
                                           adb + (gk >> 2) * 1024 + (gk & 3) * 2,
                                           bdb + (ks >> 2) * 512  + (ks & 3) * 2,
                                           MMA_IDESC, gk > 0);
                        }
                        TCGEN05_COMMIT_MC_CG2(sb + BAR_BEMPTY(c), 0x3);
                    }
                    TCGEN05_COMMIT_MC_CG2(sb + BAR_DFULL(b), 0x3);
                    gt++;
                }
            }
        }
    } else {
        // ------- epilogue: 16 warps, software-pipelined LDTM, per-cgrp barriers -------
        const int subp = wid & 3;
        const int cgrp = wid >> 2;
        float2* smcm = (float2*)(smem_raw_g + SM_CM);
        float* tbuf  = (float*)(smem_raw_g + SM_TB + wid * 1152);
        const int cq = lane & 7, rq = lane >> 3;
        const int barid = 4 + cgrp;
        const int ntile = (u1 - u0) * TPU;

        uint32_t r[32];
        // prologue: wait + issue LDTM for tile 0 (async until WAIT_LD)
        MBARRIER_WAIT_PARITY(sb + BAR_DFULL(0), 0);
        TCGEN05_FENCE_AFTER();
        TCGEN05_LD_32X32B_X32(r, tmem + cgrp * 32);

        float m2 = -INFINITY, sum = 0.f;
        for (int gt = 0; gt < ntile; gt++) {
            const int u = u0 + (gt >> 4);
            const int k = gt & 15;
            const int band = u >> 3, chunk = u & 7;
            const int tc = chunk * TPU + k;
            const int b = gt & 3;
            const int par = gt & 1;

            TCGEN05_WAIT_LD();                 // tile gt's data lands in r
            float v[32];
            #pragma unroll
            for (int j = 0; j < 32; j++) v[j] = __uint_as_float(r[j]) * C1F;
            TCGEN05_FENCE_BEFORE();
            if (lane == 0) MBARRIER_ARRIVE_LEADER(sb + BAR_DEMPTY(b));

            // prefetch next tile's LDTM (overlaps with compute below)
            if (gt + 1 < ntile) {
                const int nb = (gt + 1) & 3;
                MBARRIER_WAIT_PARITY(sb + BAR_DFULL(nb), ((gt + 1) >> 2) & 1);
                TCGEN05_FENCE_AFTER();
                TCGEN05_LD_32X32B_X32(r, tmem + nb * 128 + cgrp * 32);
            }

            // row pass (serial chains, single accumulators)
            float bm = v[0];
            #pragma unroll
            for (int j = 1; j < 32; j++) bm = fmaxf(bm, v[j]);
            const float mn = fmaxf(m2, bm);
            float acc = 0.f;
            #pragma unroll
            for (int j = 0; j < 32; j++) acc += ex2f(v[j] - mn);
            sum = fmaf(sum, ex2f(m2 - mn), acc);
            m2 = mn;

            // col pass: batched smem transpose (8 cols per batch)
            #pragma unroll
            for (int bb = 0; bb < 4; bb++) {
                __syncwarp();
                #pragma unroll
                for (int i = 0; i < 8; i++) tbuf[lane * 9 + i] = v[bb * 8 + i];
                __syncwarp();
                float rv[8];
                #pragma unroll
                for (int rr = 0; rr < 8; rr++) rv[rr] = tbuf[(rq * 8 + rr) * 9 + cq];
                float cm = rv[0];
                #pragma unroll
                for (int rr = 1; rr < 8; rr++) cm = fmaxf(cm, rv[rr]);
                cm = fmaxf(cm, __shfl_xor_sync(0xFFFFFFFFu, cm, 8));
                cm = fmaxf(cm, __shfl_xor_sync(0xFFFFFFFFu, cm, 16));
                float e = 0.f;
                #pragma unroll
                for (int rr = 0; rr < 8; rr++) e += ex2f(rv[rr] - cm);
                e += __shfl_xor_sync(0xFFFFFFFFu, e, 8);
                e += __shfl_xor_sync(0xFFFFFFFFu, e, 16);
                if (lane < 8)
                    smcm[(par * 128 + cgrp * 32 + bb * 8 + lane) * 4 + subp] = make_float2(cm, e);
            }
            asm volatile("bar.sync %0, 128;" :: "r"(barid) : "memory");
            if (lane < 8) {
                const int col = cgrp * 32 + subp * 8 + lane;
                float2 a = smcm[(par * 128 + col) * 4 + 0];
                float mm = a.x, ss = a.y;
                #pragma unroll
                for (int s = 1; s < 4; s++) {
                    float2 c2 = smcm[(par * 128 + col) * 4 + s];
                    const float nm2 = fmaxf(mm, c2.x);
                    ss = ss * ex2f(mm - nm2) + c2.y * ex2f(c2.x - nm2);
                    mm = nm2;
                }
                g_colp[(size_t)(band * 2 + (int)rank) * N_ROWS + tc * 128 + col] = make_float2(mm, ss);
            }

            if (k == 15) {
                g_rowp[(size_t)(u * 4 + cgrp) * 256 + (int)rank * 128 + subp * 32 + lane] = make_float2(m2, sum);
                m2 = -INFINITY; sum = 0.f;
            }
        }
    }

    __syncthreads();
    CLUSTER_SYNC();
    if (wid == 16) {
        TCGEN05_RELINQ_CG2();
        TCGEN05_DEALLOC_CG2(tmem, 512);
    }
    CLUSTER_SYNC();
#endif  // HAS_TC
}

// ================= merge partials into g_lse =================
__global__ void merge_row_kernel() {
    const int r = blockIdx.x * 256 + threadIdx.x;
    const int band = r >> 8, lr = r & 255;
    float m = -INFINITY, s = 0.f;
    #pragma unroll
    for (int cu = 0; cu < 32; cu++) {
        const int chunk = cu >> 2, cg = cu & 3;
        float2 pp = g_rowp[(size_t)(((band * 8 + chunk) * 4) + cg) * 256 + lr];
        const float nm = fmaxf(m, pp.x);
        s = s * ex2f(m - nm) + pp.y * ex2f(pp.x - nm);
        m = nm;
    }
    g_lse[r] = (m + lg2f(s)) * LN2F;
}

__global__ void merge_col_kernel() {
    const int c = blockIdx.x * 256 + threadIdx.x;
    float m = -INFINITY, s = 0.f;
    for (int kb = 0; kb < 128; kb++) {
        float2 pp = g_colp[(size_t)kb * N_ROWS + c];
        const float nm = fmaxf(m, pp.x);
        s = s * ex2f(m - nm) + pp.y * ex2f(pp.x - nm);
        m = nm;
    }
    g_lse[N_ROWS + c] = (m + lg2f(s)) * LN2F;
}

// ================= final reduction (deterministic) =================
__global__ void reduce1_kernel() {
    __shared__ double sm[256];
    const int base = blockIdx.x * 512;
    double pp = 0.0;
    for (int k = threadIdx.x; k < 512; k += 256) {
        const int i = base + k;
        pp += (double)g_lse[i] + (double)g_lse[N_ROWS + i] - 2.0 * (double)g_diag[i];
    }
    sm[threadIdx.x] = pp;
    __syncthreads();
    for (int o = 128; o; o >>= 1) {
        if (threadIdx.x < o) sm[threadIdx.x] += sm[threadIdx.x + o];
        __syncthreads();
    }
    if (threadIdx.x == 0) g_part[blockIdx.x] = sm[0];
}

__global__ void reduce2_kernel(float* __restrict__ out) {
    double pp = g_part[threadIdx.x];
    #pragma unroll
    for (int o = 16; o; o >>= 1) pp += __shfl_xor_sync(0xFFFFFFFFu, pp, o);
    if (threadIdx.x == 0) out[0] = (float)(pp / (2.0 * N_ROWS));
}

// ================= host =================
typedef CUresult (*EncodeTiledFn)(CUtensorMap*, CUtensorMapDataType, cuuint32_t, void*,
                                  const cuuint64_t*, const cuuint64_t*, const cuuint32_t*,
                                  const cuuint32_t*, CUtensorMapInterleave, CUtensorMapSwizzle,
                                  CUtensorMapL2promotion, CUtensorMapFloatOOBfill);

static void make_map(EncodeTiledFn fn, CUtensorMap* m, void* ptr) {
    cuuint64_t dims[3]    = {DIM, N_ROWS, 1};
    cuuint64_t strides[2] = {DIM * 2ull, (cuuint64_t)N_ROWS * DIM * 2ull};
    cuuint32_t box[3]     = {64, 64, 1};
    cuuint32_t es[3]      = {1, 1, 1};
    fn(m, CU_TENSOR_MAP_DATA_TYPE_BFLOAT16, 3, ptr, dims, strides, box, es,
       CU_TENSOR_MAP_INTERLEAVE_NONE, CU_TENSOR_MAP_SWIZZLE_128B,
       CU_TENSOR_MAP_L2_PROMOTION_L2_128B, CU_TENSOR_MAP_FLOAT_OOB_FILL_NONE);
}

extern "C" void kernel_launch(void* const* d_in, const int* in_sizes, int n_in,
                              void* d_out, int out_size) {
    const float* img = (const float*)d_in[0];
    const float* txt = (const float*)d_in[1];

    conv_diag_kernel<<<2048, 256>>>(img, txt);

    void* pimg = nullptr; void* ptxt = nullptr;
    cudaGetSymbolAddress(&pimg, g_img_bf);
    cudaGetSymbolAddress(&ptxt, g_txt_bf);

    EncodeTiledFn enc = nullptr;
    cudaDriverEntryPointQueryResult qr;
    cudaGetDriverEntryPointByVersion("cuTensorMapEncodeTiled", (void**)&enc, 12000,
                                     cudaEnableDefault, &qr);
    CUtensorMap tm_img, tm_txt;
    make_map(enc, &tm_img, pimg);
    make_map(enc, &tm_txt, ptxt);

    cudaFuncSetAttribute(clip_gemm_tc,
                         cudaFuncAttributeMaxDynamicSharedMemorySize, SMEM_TOTAL_TC);
    clip_gemm_tc<<<GRID_TC, NTHR, SMEM_TOTAL_TC>>>(tm_img, tm_txt);

    merge_row_kernel<<<64, 256>>>();
    merge_col_kernel<<<64, 256>>>();
    reduce1_kernel<<<32, 256>>>();
    reduce2_kernel<<<1, 32>>>((float*)d_out);
}

// round 16
// speedup vs baseline: 1.0872x; 1.0872x over previous
#include <cuda_runtime.h>
#include <cuda.h>
#include <cuda_bf16.h>
#include <cstdint>
#include <math.h>

#define N_ROWS 16384
#define DIM    512
#define SCALEF 14.285714285714286f
#define C1F    20.609928468897677f   /* SCALE * log2(e) */
#define LN2F   0.6931471805599453f

#if defined(__CUDA_ARCH__) && (defined(__CUDA_ARCH_FEAT_SM103_ALL) || defined(__CUDA_ARCH_FEAT_SM100_ALL) || defined(__CUDA_ARCH_FEAT_SM101_ALL))
#define HAS_TC 1
#else
#define HAS_TC 0
#endif

#define NPAIRS 74
#define GRID_TC 148
#define NUNITS 512
#define TPU    16
#define NTHR   576

#define BAR_AFULL   0
#define BAR_BFULL(c)   (8  + 8*(c))
#define BAR_BEMPTY(c)  (40 + 8*(c))
#define BAR_DEMPTY(b)  (72 + 8*(b))
#define BAR_DFULL(b)   (88 + 8*(b))
#define SM_TPTR     104
#define SM_A        1024
#define SM_B        (1024 + 131072)
#define SM_CM       (1024 + 131072 + 65536)
#define SM_TB       (SM_CM + 8192)
#define SMEM_TOTAL_TC  (SM_TB + 16 * 1152)

#define MMA_IDESC 0x10200490u   /* f32 acc, bf16 x bf16, M=256, N=128 */

__device__ __align__(1024) __nv_bfloat16 g_img_bf[(size_t)N_ROWS * DIM];
__device__ __align__(1024) __nv_bfloat16 g_txt_bf[(size_t)N_ROWS * DIM];
__device__ float2 g_rowp[(size_t)NUNITS * 4 * 256];
__device__ float2 g_colp[(size_t)128 * N_ROWS];
__device__ float  g_lse[2 * N_ROWS];
__device__ float  g_diag[N_ROWS];
__device__ double g_part[32];

__device__ __forceinline__ float ex2f(float x) { float y; asm("ex2.approx.f32 %0, %1;" : "=f"(y) : "f"(x)); return y; }
__device__ __forceinline__ float lg2f(float x) { float y; asm("lg2.approx.f32 %0, %1;" : "=f"(y) : "f"(x)); return y; }

__global__ void conv_diag_kernel(const float* __restrict__ img, const float* __restrict__ txt) {
    const int row  = blockIdx.x * 8 + (threadIdx.x >> 5);
    const int lane = threadIdx.x & 31;
    const float4* ai = (const float4*)(img + (size_t)row * DIM);
    const float4* bi = (const float4*)(txt + (size_t)row * DIM);
    __nv_bfloat162* ao = (__nv_bfloat162*)(g_img_bf + (size_t)row * DIM);
    __nv_bfloat162* bo = (__nv_bfloat162*)(g_txt_bf + (size_t)row * DIM);
    float dot = 0.f;
    #pragma unroll
    for (int t = 0; t < 4; t++) {
        const int i = lane + 32 * t;
        float4 a = ai[i], b = bi[i];
        ao[2 * i]     = __float22bfloat162_rn(make_float2(a.x, a.y));
        ao[2 * i + 1] = __float22bfloat162_rn(make_float2(a.z, a.w));
        bo[2 * i]     = __float22bfloat162_rn(make_float2(b.x, b.y));
        bo[2 * i + 1] = __float22bfloat162_rn(make_float2(b.z, b.w));
        dot += a.x * b.x + a.y * b.y + a.z * b.z + a.w * b.w;
    }
    #pragma unroll
    for (int o = 16; o; o >>= 1) dot += __shfl_xor_sync(0xFFFFFFFFu, dot, o);
    if (lane == 0) g_diag[row] = SCALEF * dot;
}

#if HAS_TC
__device__ __forceinline__ uint32_t smem_u32(const void* p) {
    uint32_t a;
    asm("{ .reg .u64 t; cvta.to.shared.u64 t, %1; cvt.u32.u64 %0, t; }" : "=r"(a) : "l"(p));
    return a;
}
__device__ __forceinline__ uint32_t elect_one() {
    uint32_t pred;
    asm volatile("{\n\t.reg .pred p;\n\telect.sync _|p, 0xFFFFFFFF;\n\tselp.b32 %0, 1, 0, p;\n\t}" : "=r"(pred));
    return pred;
}
__device__ __forceinline__ uint32_t ctarank() {
    uint32_t r; asm("mov.u32 %0, %%cluster_ctarank;" : "=r"(r)); return r;
}

#define MBARRIER_INIT(addr, cnt) \
    asm volatile("mbarrier.init.shared.b64 [%0], %1;" :: "r"((uint32_t)(addr)), "r"((uint32_t)(cnt)) : "memory")
#define MBARRIER_EXPECT_TX(addr, bytes) \
    asm volatile("mbarrier.arrive.expect_tx.shared.b64 _, [%0], %1;" :: "r"((uint32_t)(addr)), "r"((uint32_t)(bytes)) : "memory")
#define MBARRIER_ARRIVE_LEADER(addr) \
    asm volatile("{\n\t.reg .b32 la;\n\tand.b32 la, %0, 0xFEFFFFFF;\n\t" \
                 "mbarrier.arrive.shared::cluster.b64 _, [la];\n\t}" :: "r"((uint32_t)(addr)) : "memory")
#define MBARRIER_WAIT_PARITY(addr, par) do {                                      \
    uint32_t _m = (uint32_t)(addr), _p = (uint32_t)(par), _d;                     \
    asm volatile("{\n\t.reg .pred p;\n\t"                                         \
        "mbarrier.try_wait.parity.acquire.cta.shared::cta.b64 p, [%1], %2;\n\t"   \
        "selp.b32 %0, 1, 0, p;\n\t}" : "=r"(_d) : "r"(_m), "r"(_p) : "memory");   \
    if (!_d) {                                                                    \
        asm volatile("{\n\t.reg .pred P1;\n\t"                                    \
            "WL_%=:\n\t"                                                          \
            "mbarrier.try_wait.parity.acquire.cta.shared::cta.b64 P1, [%0], %1, 0x989680;\n\t" \
            "@P1 bra.uni WD_%=;\n\t"                                              \
            "bra.uni WL_%=;\n\t"                                                  \
            "WD_%=:\n\t}" :: "r"(_m), "r"(_p) : "memory");                        \
    } } while (0)

#define CLUSTER_SYNC() do { \
    asm volatile("barrier.cluster.arrive.aligned;" ::: "memory"); \
    asm volatile("barrier.cluster.wait.aligned;"   ::: "memory"); } while (0)

#define TCGEN05_ALLOC_CG2(sm, n) \
    asm volatile("tcgen05.alloc.cta_group::2.sync.aligned.shared::cta.b32 [%0], %1;" \
                 :: "r"((uint32_t)(sm)), "r"((uint32_t)(n)) : "memory")
#define TCGEN05_DEALLOC_CG2(t, n) \
    asm volatile("tcgen05.dealloc.cta_group::2.sync.aligned.b32 %0, %1;" :: "r"(t), "r"((uint32_t)(n)))
#define TCGEN05_RELINQ_CG2() \
    asm volatile("tcgen05.relinquish_alloc_permit.cta_group::2.sync.aligned;")
#define TCGEN05_COMMIT_MC_CG2(bar, mask) \
    asm volatile("tcgen05.commit.cta_group::2.mbarrier::arrive::one.shared::cluster.multicast::cluster.b64 [%0], %1;" \
                 :: "r"((uint32_t)(bar)), "h"((uint16_t)(mask)) : "memory")
#define TCGEN05_FENCE_BEFORE() asm volatile("tcgen05.fence::before_thread_sync;" ::: "memory")
#define TCGEN05_FENCE_AFTER()  asm volatile("tcgen05.fence::after_thread_sync;" ::: "memory")
#define TCGEN05_WAIT_LD()      asm volatile("tcgen05.wait::ld.sync.aligned;" ::: "memory")

#define TCGEN05_LD_32X32B_X32(r, ta) \
    asm volatile("tcgen05.ld.sync.aligned.32x32b.x32.b32 " \
        "{%0, %1, %2, %3, %4, %5, %6, %7, %8, %9, %10, %11, %12, %13, %14, %15, " \
        " %16, %17, %18, %19, %20, %21, %22, %23, %24, %25, %26, %27, %28, %29, %30, %31}, [%32];" \
        : "=r"((r)[0]),  "=r"((r)[1]),  "=r"((r)[2]),  "=r"((r)[3]), \
          "=r"((r)[4]),  "=r"((r)[5]),  "=r"((r)[6]),  "=r"((r)[7]), \
          "=r"((r)[8]),  "=r"((r)[9]),  "=r"((r)[10]), "=r"((r)[11]), \
          "=r"((r)[12]), "=r"((r)[13]), "=r"((r)[14]), "=r"((r)[15]), \
          "=r"((r)[16]), "=r"((r)[17]), "=r"((r)[18]), "=r"((r)[19]), \
          "=r"((r)[20]), "=r"((r)[21]), "=r"((r)[22]), "=r"((r)[23]), \
          "=r"((r)[24]), "=r"((r)[25]), "=r"((r)[26]), "=r"((r)[27]), \
          "=r"((r)[28]), "=r"((r)[29]), "=r"((r)[30]), "=r"((r)[31]) \
        : "r"(ta))

#define TMA_LOAD_3D_CG2(dst, map, x, y, z, bar) \
    asm volatile("{\n\t.reg .b32 lb;\n\tand.b32 lb, %5, 0xFEFFFFFF;\n\t" \
        "cp.async.bulk.tensor.3d.cta_group::2.shared::cluster.global" \
        ".tile.mbarrier::complete_tx::bytes [%0], [%1, {%2, %3, %4}], [lb];\n\t}" \
        :: "r"((uint32_t)(dst)), "l"(map), "r"((int32_t)(x)), "r"((int32_t)(y)), "r"((int32_t)(z)), \
           "r"((uint32_t)(bar)) : "memory")

static constexpr uint64_t SMEM_DESC_BASE_SW128 =
    (uint64_t(2)  << 61) | (uint64_t(1) << 46) | (uint64_t(64) << 32) | (uint64_t(1) << 16);
#define MAKE_SMEM_DESC(a) (SMEM_DESC_BASE_SW128 | ((uint64_t)((a) >> 4) & 0x3FFF))

__device__ __forceinline__ void mma_f16_ss_cg2(uint32_t d, uint64_t a, uint64_t b,
                                               uint32_t idesc, uint32_t en) {
    asm volatile("{\n\t.reg .pred p;\n\tsetp.ne.u32 p, %5, 0;\n\t"
        "tcgen05.mma.cta_group::2.kind::f16 [%0], %1, %2, %3, "
        "{%4, %4, %4, %4, %4, %4, %4, %4}, p;\n\t}"
        :: "r"(d), "l"(a), "l"(b), "r"(idesc), "r"(0u), "r"(en) : "memory");
}
#endif  // HAS_TC helpers

extern __shared__ char smem_raw_g[];

__global__ void __launch_bounds__(NTHR, 1) __cluster_dims__(2, 1, 1)
clip_gemm_tc(const __grid_constant__ CUtensorMap tm_img,
             const __grid_constant__ CUtensorMap tm_txt) {
#if HAS_TC
    uint32_t sb = smem_u32(smem_raw_g);
    const int tid  = threadIdx.x;
    const int wid  = tid >> 5;
    const int lane = tid & 31;
    const uint32_t rank = ctarank();
    const int p = blockIdx.x >> 1;
    const int u0 = (p * NUNITS) / NPAIRS;
    const int u1 = ((p + 1) * NUNITS) / NPAIRS;

    if (wid == 16) TCGEN05_ALLOC_CG2(sb + SM_TPTR, 256);
    if (tid == 0) {
        MBARRIER_INIT(sb + BAR_AFULL, 1);
        #pragma unroll
        for (int c = 0; c < 4; c++) {
            MBARRIER_INIT(sb + BAR_BFULL(c), 1);
            MBARRIER_INIT(sb + BAR_BEMPTY(c), 1);
        }
        MBARRIER_INIT(sb + BAR_DEMPTY(0), 32);
        MBARRIER_INIT(sb + BAR_DEMPTY(1), 32);
        MBARRIER_INIT(sb + BAR_DFULL(0), 1);
        MBARRIER_INIT(sb + BAR_DFULL(1), 1);
    }
    __syncthreads();
    uint32_t tmem;
    asm volatile("ld.shared.b32 %0, [%1];" : "=r"(tmem) : "r"(sb + SM_TPTR));
    CLUSTER_SYNC();

    if (wid == 16) {
        // ---------------- producer: TMA issue ----------------
        if (elect_one()) {
            int gt = 0, prev_band = -1;
            for (int u = u0; u < u1; u++) {
                const int band = u >> 3, chunk = u & 7;
                if (band != prev_band) {
                    if (gt > 0) MBARRIER_WAIT_PARITY(sb + BAR_BEMPTY(3), (gt & 1) ^ 1);
                    if (rank == 0) MBARRIER_EXPECT_TX(sb + BAR_AFULL, 262144);
                    const int arow = band * 256 + (int)rank * 128;
                    #pragma unroll
                    for (int k8 = 0; k8 < 8; k8++)
                        #pragma unroll
                        for (int r64 = 0; r64 < 2; r64++)
                            TMA_LOAD_3D_CG2(sb + SM_A + k8 * 16384 + r64 * 8192, &tm_img,
                                            k8 * 64, arow + r64 * 64, 0, sb + BAR_AFULL);
                    prev_band = band;
                }
                for (int k = 0; k < TPU; k++) {
                    const int tc = chunk * TPU + k;
                    #pragma unroll
                    for (int c = 0; c < 4; c++) {
                        MBARRIER_WAIT_PARITY(sb + BAR_BEMPTY(c), (gt & 1) ^ 1);
                        if (rank == 0) MBARRIER_EXPECT_TX(sb + BAR_BFULL(c), 32768);
                        const int y = tc * 128 + (int)rank * 64;
                        TMA_LOAD_3D_CG2(sb + SM_B + c * 16384,        &tm_txt, c * 128,      y, 0, sb + BAR_BFULL(c));
                        TMA_LOAD_3D_CG2(sb + SM_B + c * 16384 + 8192, &tm_txt, c * 128 + 64, y, 0, sb + BAR_BFULL(c));
                    }
                    gt++;
                }
            }
        }
    } else if (wid == 17) {
        // ---------------- MMA issuer (leader only) ----------------
        if (rank == 0 && elect_one()) {
            int gt = 0, lb = 0, prev_band = -1;
            const uint64_t adb = MAKE_SMEM_DESC(sb + SM_A);
            for (int u = u0; u < u1; u++) {
                const int band = u >> 3;
                if (band != prev_band) {
                    MBARRIER_WAIT_PARITY(sb + BAR_AFULL, lb & 1);
                    lb++; prev_band = band;
                }
                for (int k = 0; k < TPU; k++) {
                    const int b = gt & 1;
                    MBARRIER_WAIT_PARITY(sb + BAR_DEMPTY(b), ((gt >> 1) & 1) ^ 1);
                    TCGEN05_FENCE_AFTER();
                    #pragma unroll
                    for (int c = 0; c < 4; c++) {
                        MBARRIER_WAIT_PARITY(sb + BAR_BFULL(c), gt & 1);
                        const uint64_t bdb = MAKE_SMEM_DESC(sb + SM_B + c * 16384);
                        #pragma unroll
                        for (int ks = 0; ks < 8; ks++) {
                            const int gk = c * 8 + ks;
                            mma_f16_ss_cg2(tmem + b * 128,
                                           adb + (gk >> 2) * 1024 + (gk & 3) * 2,
                                           bdb + (ks >> 2) * 512  + (ks & 3) * 2,
                                           MMA_IDESC, gk > 0);
                        }
                        TCGEN05_COMMIT_MC_CG2(sb + BAR_BEMPTY(c), 0x3);
                    }
                    TCGEN05_COMMIT_MC_CG2(sb + BAR_DFULL(b), 0x3);
                    gt++;
                }
            }
        }
    } else {
        // ------- epilogue: 16 warps, R14 structure (wait-at-top, 2 D buffers) -------
        const int subp = wid & 3;
        const int cgrp = wid >> 2;
        float2* smcm = (float2*)(smem_raw_g + SM_CM);
        float* tbuf  = (float*)(smem_raw_g + SM_TB + wid * 1152);
        const int cq = lane & 7, rq = lane >> 3;
        const int barid = 4 + cgrp;
        int gt = 0;
        for (int u = u0; u < u1; u++) {
            const int band = u >> 3, chunk = u & 7;
            float m2 = -INFINITY, sum = 0.f;
            for (int k = 0; k < TPU; k++) {
                const int tc = chunk * TPU + k;
                const int b  = gt & 1;
                const int par = gt & 1;
                MBARRIER_WAIT_PARITY(sb + BAR_DFULL(b), (gt >> 1) & 1);
                TCGEN05_FENCE_AFTER();
                uint32_t r[32];
                TCGEN05_LD_32X32B_X32(r, tmem + b * 128 + cgrp * 32);
                TCGEN05_WAIT_LD();
                TCGEN05_FENCE_BEFORE();
                if (lane == 0) MBARRIER_ARRIVE_LEADER(sb + BAR_DEMPTY(b));

                float v[32];
                #pragma unroll
                for (int j = 0; j < 32; j++) v[j] = __uint_as_float(r[j]) * C1F;

                // row pass (serial chains, single accumulators)
                float bm = v[0];
                #pragma unroll
                for (int j = 1; j < 32; j++) bm = fmaxf(bm, v[j]);
                const float mn = fmaxf(m2, bm);
                float acc = 0.f;
                #pragma unroll
                for (int j = 0; j < 32; j++) acc += ex2f(v[j] - mn);
                sum = fmaf(sum, ex2f(m2 - mn), acc);
                m2 = mn;

                // col pass: batched smem transpose (8 cols per batch)
                #pragma unroll
                for (int bb = 0; bb < 4; bb++) {
                    __syncwarp();
                    #pragma unroll
                    for (int i = 0; i < 8; i++) tbuf[lane * 9 + i] = v[bb * 8 + i];
                    __syncwarp();
                    float rv[8];
                    #pragma unroll
                    for (int rr = 0; rr < 8; rr++) rv[rr] = tbuf[(rq * 8 + rr) * 9 + cq];
                    float cm = rv[0];
                    #pragma unroll
                    for (int rr = 1; rr < 8; rr++) cm = fmaxf(cm, rv[rr]);
                    cm = fmaxf(cm, __shfl_xor_sync(0xFFFFFFFFu, cm, 8));
                    cm = fmaxf(cm, __shfl_xor_sync(0xFFFFFFFFu, cm, 16));
                    float e = 0.f;
                    #pragma unroll
                    for (int rr = 0; rr < 8; rr++) e += ex2f(rv[rr] - cm);
                    e += __shfl_xor_sync(0xFFFFFFFFu, e, 8);
                    e += __shfl_xor_sync(0xFFFFFFFFu, e, 16);
                    if (lane < 8)
                        smcm[(par * 128 + cgrp * 32 + bb * 8 + lane) * 4 + subp] = make_float2(cm, e);
                }
                asm volatile("bar.sync %0, 128;" :: "r"(barid) : "memory");
                if (lane < 8) {
                    const int col = cgrp * 32 + subp * 8 + lane;
                    float2 a = smcm[(par * 128 + col) * 4 + 0];
                    float mm = a.x, ss = a.y;
                    #pragma unroll
                    for (int s = 1; s < 4; s++) {
                        float2 c2 = smcm[(par * 128 + col) * 4 + s];
                        const float nm2 = fmaxf(mm, c2.x);
                        ss = ss * ex2f(mm - nm2) + c2.y * ex2f(c2.x - nm2);
                        mm = nm2;
                    }
                    g_colp[(size_t)(band * 2 + (int)rank) * N_ROWS + tc * 128 + col] = make_float2(mm, ss);
                }
                gt++;
            }
            g_rowp[(size_t)(u * 4 + cgrp) * 256 + (int)rank * 128 + subp * 32 + lane] = make_float2(m2, sum);
        }
    }

    __syncthreads();
    CLUSTER_SYNC();
    if (wid == 16) {
        TCGEN05_RELINQ_CG2();
        TCGEN05_DEALLOC_CG2(tmem, 256);
    }
    CLUSTER_SYNC();
#endif  // HAS_TC
}

// ========== fused merge kernel: full chip coverage ==========
// grid = 384 x 128: blocks 0..127 rows; blocks 128..383 cols (2-way split).
__global__ void merge_kernel() {
    const int bid = blockIdx.x;
    if (bid < 128) {
        const int r = bid * 128 + threadIdx.x;         // 16384 rows
        const int band = r >> 8, lr = r & 255;
        float m = -INFINITY, s = 0.f;
        #pragma unroll
        for (int cu = 0; cu < 32; cu++) {
            const int chunk = cu >> 2, cg = cu & 3;
            float2 pp = g_rowp[(size_t)(((band * 8 + chunk) * 4) + cg) * 256 + lr];
            const float nm = fmaxf(m, pp.x);
            s = s * ex2f(m - nm) + pp.y * ex2f(pp.x - nm);
            m = nm;
        }
        g_lse[r] = (m + lg2f(s)) * LN2F;
    } else {
        // 2 threads per column: each folds 64 contributions, shfl-merged
        const int gidx = (bid - 128) * 128 + threadIdx.x;   // 0..32767
        const int c = gidx >> 1, h = gidx & 1;
        float m = -INFINITY, s = 0.f;
        for (int i = 0; i < 64; i++) {
            float2 pp = g_colp[(size_t)(h * 64 + i) * N_ROWS + c];
            const float nm = fmaxf(m, pp.x);
            s = s * ex2f(m - nm) + pp.y * ex2f(pp.x - nm);
            m = nm;
        }
        const float mo = __shfl_xor_sync(0xFFFFFFFFu, m, 1);
        const float so = __shfl_xor_sync(0xFFFFFFFFu, s, 1);
        const float nm = fmaxf(m, mo);
        s = s * ex2f(m - nm) + so * ex2f(mo - nm);
        if (h == 0) g_lse[N_ROWS + c] = (nm + lg2f(s)) * LN2F;
    }
}

// ================= final reduction (deterministic) =================
__global__ void reduce1_kernel() {
    __shared__ double sm[256];
    const int base = blockIdx.x * 512;
    double pp = 0.0;
    for (int k = threadIdx.x; k < 512; k += 256) {
        const int i = base + k;
        pp += (double)g_lse[i] + (double)g_lse[N_ROWS + i] - 2.0 * (double)g_diag[i];
    }
    sm[threadIdx.x] = pp;
    __syncthreads();
    for (int o = 128; o; o >>= 1) {
        if (threadIdx.x < o) sm[threadIdx.x] += sm[threadIdx.x + o];
        __syncthreads();
    }
    if (threadIdx.x == 0) g_part[blockIdx.x] = sm[0];
}

__global__ void reduce2_kernel(float* __restrict__ out) {
    double pp = g_part[threadIdx.x];
    #pragma unroll
    for (int o = 16; o; o >>= 1) pp += __shfl_xor_sync(0xFFFFFFFFu, pp, o);
    if (threadIdx.x == 0) out[0] = (float)(pp / (2.0 * N_ROWS));
}

// ================= host =================
typedef CUresult (*EncodeTiledFn)(CUtensorMap*, CUtensorMapDataType, cuuint32_t, void*,
                                  const cuuint64_t*, const cuuint64_t*, const cuuint32_t*,
                                  const cuuint32_t*, CUtensorMapInterleave, CUtensorMapSwizzle,
                                  CUtensorMapL2promotion, CUtensorMapFloatOOBfill);

static void make_map(EncodeTiledFn fn, CUtensorMap* m, void* ptr) {
    cuuint64_t dims[3]    = {DIM, N_ROWS, 1};
    cuuint64_t strides[2] = {DIM * 2ull, (cuuint64_t)N_ROWS * DIM * 2ull};
    cuuint32_t box[3]     = {64, 64, 1};
    cuuint32_t es[3]      = {1, 1, 1};
    fn(m, CU_TENSOR_MAP_DATA_TYPE_BFLOAT16, 3, ptr, dims, strides, box, es,
       CU_TENSOR_MAP_INTERLEAVE_NONE, CU_TENSOR_MAP_SWIZZLE_128B,
       CU_TENSOR_MAP_L2_PROMOTION_L2_128B, CU_TENSOR_MAP_FLOAT_OOB_FILL_NONE);
}

extern "C" void kernel_launch(void* const* d_in, const int* in_sizes, int n_in,
                              void* d_out, int out_size) {
    const float* img = (const float*)d_in[0];
    const float* txt = (const float*)d_in[1];

    conv_diag_kernel<<<2048, 256>>>(img, txt);

    void* pimg = nullptr; void* ptxt = nullptr;
    cudaGetSymbolAddress(&pimg, g_img_bf);
    cudaGetSymbolAddress(&ptxt, g_txt_bf);

    EncodeTiledFn enc = nullptr;
    cudaDriverEntryPointQueryResult qr;
    cudaGetDriverEntryPointByVersion("cuTensorMapEncodeTiled", (void**)&enc, 12000,
                                     cudaEnableDefault, &qr);
    CUtensorMap tm_img, tm_txt;
    make_map(enc, &tm_img, pimg);
    make_map(enc, &tm_txt, ptxt);

    cudaFuncSetAttribute(clip_gemm_tc,
                         cudaFuncAttributeMaxDynamicSharedMemorySize, SMEM_TOTAL_TC);
    clip_gemm_tc<<<GRID_TC, NTHR, SMEM_TOTAL_TC>>>(tm_img, tm_txt);

    merge_kernel<<<384, 128>>>();
    reduce1_kernel<<<32, 256>>>();
    reduce2_kernel<<<1, 32>>>((float*)d_out);
}